// round 1
// baseline (speedup 1.0000x reference)
#include <cuda_runtime.h>
#include <float.h>

// Problem constants (fixed by setup_inputs)
#define S_    1600
#define DIM_  384
#define NH_   6
#define DH_   64
#define INNER_ 384
#define HID_  1536
#define NL_   6
#define GW_   40
#define TOPK_ 32
#define SCALE_ 0.05103103630798288f   // 384^-0.5

// ---------------- device scratch (no allocations allowed) ----------------
__device__ float g_h[S_*DIM_];
__device__ float g_n[S_*DIM_];
__device__ float g_q[NH_*S_*DH_];
__device__ float g_k[NH_*S_*DH_];
__device__ float g_v[NH_*S_*DH_];
__device__ float g_pb[NH_*S_*64];                 // 49 buckets padded to 64
__device__ float g_scores[(long long)NH_*S_*S_];  // 61.4 MB
__device__ float g_att[S_*INNER_];
__device__ float g_ff1[S_*HID_];

// ---------------- trivial copy kernels ----------------
__global__ void init_h_kernel(const float* __restrict__ x) {
    int i = blockIdx.x * blockDim.x + threadIdx.x;
    if (i < S_*DIM_) g_h[i] = x[i];
}
__global__ void write_out_kernel(float* __restrict__ out) {
    int i = blockIdx.x * blockDim.x + threadIdx.x;
    if (i < S_*DIM_) out[i] = g_h[i];
}

// ---------------- LayerNorm: reads g_h, writes g_n ----------------
__global__ void ln_kernel(const float* __restrict__ gamma, const float* __restrict__ beta) {
    int row = blockIdx.x;
    const float* x = g_h + row * DIM_;
    float s = 0.f, s2 = 0.f;
    for (int i = threadIdx.x; i < DIM_; i += blockDim.x) { float v = x[i]; s += v; s2 += v*v; }
    for (int o = 16; o; o >>= 1) {
        s  += __shfl_xor_sync(0xffffffffu, s,  o);
        s2 += __shfl_xor_sync(0xffffffffu, s2, o);
    }
    __shared__ float rs[4], rs2[4];
    int w = threadIdx.x >> 5;
    if ((threadIdx.x & 31) == 0) { rs[w] = s; rs2[w] = s2; }
    __syncthreads();
    s  = rs[0]  + rs[1]  + rs[2]  + rs[3];
    s2 = rs2[0] + rs2[1] + rs2[2] + rs2[3];
    float mean = s * (1.f / DIM_);
    float var  = s2 * (1.f / DIM_) - mean * mean;
    float inv  = rsqrtf(var + 1e-5f);
    for (int i = threadIdx.x; i < DIM_; i += blockDim.x)
        g_n[row*DIM_ + i] = (x[i] - mean) * inv * gamma[i] + beta[i];
}

// ---------------- shared fp32 tiled GEMM: C[1600 x N] = A[1600 x K] @ B[K x N] ----------------
// MODE 0: A=g_n,  QKV scatter epilogue (stride-3 interleave -> g_q/g_k/g_v head-major)
// MODE 1: A=g_att, g_h += acc                      (Wo + residual)
// MODE 2: A=g_n,  g_ff1 = leaky_relu(acc+bias,0.2) (FF1)
// MODE 3: A=g_ff1, g_h += acc + bias               (FF2 + residual)
template<int MODE>
__global__ void __launch_bounds__(256) gemm_k(const float* __restrict__ B,
                                              const float* __restrict__ bias,
                                              int N, int K) {
    const float* A = (MODE == 0 || MODE == 2) ? g_n : (MODE == 1 ? g_att : g_ff1);
    __shared__ __align__(16) float As[16][68];
    __shared__ __align__(16) float Bs[16][68];
    int tid = threadIdx.x;
    int tx = tid & 15, ty = tid >> 4;
    int m0 = blockIdx.y * 64, n0 = blockIdx.x * 64;
    int arow = tid >> 2, acol = (tid & 3) * 4;
    int brow = tid >> 4, bcol = (tid & 15) * 4;
    float acc[4][4] = {};
    for (int k0 = 0; k0 < K; k0 += 16) {
        float4 av = *reinterpret_cast<const float4*>(A + (size_t)(m0 + arow) * K + k0 + acol);
        As[acol+0][arow] = av.x; As[acol+1][arow] = av.y;
        As[acol+2][arow] = av.z; As[acol+3][arow] = av.w;
        float4 bv = *reinterpret_cast<const float4*>(B + (size_t)(k0 + brow) * N + n0 + bcol);
        *reinterpret_cast<float4*>(&Bs[brow][bcol]) = bv;
        __syncthreads();
#pragma unroll
        for (int kk = 0; kk < 16; kk++) {
            float4 a4 = *reinterpret_cast<const float4*>(&As[kk][ty*4]);
            float4 b4 = *reinterpret_cast<const float4*>(&Bs[kk][tx*4]);
            float ar[4] = {a4.x, a4.y, a4.z, a4.w};
            float br[4] = {b4.x, b4.y, b4.z, b4.w};
#pragma unroll
            for (int i = 0; i < 4; i++)
#pragma unroll
                for (int j = 0; j < 4; j++)
                    acc[i][j] = fmaf(ar[i], br[j], acc[i][j]);
        }
        __syncthreads();
    }
#pragma unroll
    for (int i = 0; i < 4; i++) {
        int m = m0 + ty*4 + i;
#pragma unroll
        for (int j = 0; j < 4; j++) {
            int n = n0 + tx*4 + j;
            float v = acc[i][j];
            if (MODE == 0) {
                int idx = n / 3, r = n - idx * 3;      // qkv[..., r::3] -> (NH,DH)
                int hh = idx >> 6, d = idx & 63;
                float* dst = (r == 0) ? g_q : (r == 1) ? g_k : g_v;
                dst[(hh * S_ + m) * DH_ + d] = v;
            } else if (MODE == 1) {
                g_h[m * DIM_ + n] += v;
            } else if (MODE == 2) {
                float t = v + bias[n];
                g_ff1[m * HID_ + n] = t > 0.f ? t : 0.2f * t;
            } else {
                g_h[m * DIM_ + n] += v + bias[n];
            }
        }
    }
}

// ---------------- pb[h,q,m] = q[h,q,:] . rel_bias[m,:]  (m < 49) ----------------
__global__ void pb_kernel(const float* __restrict__ rb) {
    int hq = blockIdx.x;                 // h*S + q
    __shared__ float qs[DH_];
    if (threadIdx.x < DH_) qs[threadIdx.x] = g_q[hq * DH_ + threadIdx.x];
    __syncthreads();
    int m = threadIdx.x;
    if (m < 49) {
        float acc = 0.f;
#pragma unroll
        for (int d = 0; d < DH_; d++) acc = fmaf(qs[d], rb[m * DH_ + d], acc);
        g_pb[hq * 64 + m] = acc;
    }
}

// ---------------- scores[h,q,k] = (q.k + pb[buck(q,k)]) * SCALE ----------------
__global__ void __launch_bounds__(256) scores_kernel() {
    int h = blockIdx.z;
    const float* Q  = g_q + (size_t)h * S_ * DH_;
    const float* Km = g_k + (size_t)h * S_ * DH_;
    __shared__ __align__(16) float Qs[16][68];
    __shared__ __align__(16) float Ks[16][68];
    int tid = threadIdx.x;
    int tx = tid & 15, ty = tid >> 4;
    int m0 = blockIdx.y * 64, n0 = blockIdx.x * 64;
    int row = tid >> 2, col = (tid & 3) * 4;
    float acc[4][4] = {};
    for (int k0 = 0; k0 < DH_; k0 += 16) {
        float4 qv4 = *reinterpret_cast<const float4*>(Q + (size_t)(m0 + row) * DH_ + k0 + col);
        Qs[col+0][row] = qv4.x; Qs[col+1][row] = qv4.y;
        Qs[col+2][row] = qv4.z; Qs[col+3][row] = qv4.w;
        float4 kv4 = *reinterpret_cast<const float4*>(Km + (size_t)(n0 + row) * DH_ + k0 + col);
        Ks[col+0][row] = kv4.x; Ks[col+1][row] = kv4.y;
        Ks[col+2][row] = kv4.z; Ks[col+3][row] = kv4.w;
        __syncthreads();
#pragma unroll
        for (int kk = 0; kk < 16; kk++) {
            float4 a4 = *reinterpret_cast<const float4*>(&Qs[kk][ty*4]);
            float4 b4 = *reinterpret_cast<const float4*>(&Ks[kk][tx*4]);
            float ar[4] = {a4.x, a4.y, a4.z, a4.w};
            float br[4] = {b4.x, b4.y, b4.z, b4.w};
#pragma unroll
            for (int i = 0; i < 4; i++)
#pragma unroll
                for (int j = 0; j < 4; j++)
                    acc[i][j] = fmaf(ar[i], br[j], acc[i][j]);
        }
        __syncthreads();
    }
#pragma unroll
    for (int i = 0; i < 4; i++) {
        int q = m0 + ty*4 + i;
        int qv = q / GW_, qh = q - qv * GW_;
        const float* pbq = g_pb + ((size_t)h * S_ + q) * 64;
        float* srow = g_scores + ((size_t)h * S_ + q) * S_;
#pragma unroll
        for (int j = 0; j < 4; j++) {
            int kq = n0 + tx*4 + j;
            int kv = kq / GW_, kh = kq - kv * GW_;
            int dv = kv - qv, dh = kh - qh;
            int ad = (dv < 0 ? -dv : dv) + (dh < 0 ? -dh : dh);
            int m = (ad <= 3) ? ((dv + 3) * 7 + (dh + 3)) : 0;
            srow[kq] = (acc[i][j] + pbq[m]) * SCALE_;
        }
    }
}

// ---------------- per-row: exact top-32 radix select + softmax + sparse P.V ----------------
__global__ void __launch_bounds__(128) attn_row_kernel() {
    int bx = blockIdx.x;                 // h*S + q
    int h = bx / S_, q = bx - h * S_;
    const float* srow = g_scores + (size_t)bx * S_;
    __shared__ unsigned su[S_];
    __shared__ unsigned hist[256];
    __shared__ int   sidx[256];
    __shared__ float sval[256];
    __shared__ float smaxw[4];
    __shared__ unsigned sh_pref;
    __shared__ int sh_k, sh_cnt;
    __shared__ float sh_max, sh_inv;
    int tid = threadIdx.x, nt = blockDim.x;

    // load + order-preserving float->uint key + row max
    float mx = -FLT_MAX;
    for (int i = tid; i < S_; i += nt) {
        float v = srow[i];
        unsigned b = __float_as_uint(v);
        su[i] = (b & 0x80000000u) ? ~b : (b | 0x80000000u);
        mx = fmaxf(mx, v);
    }
    for (int o = 16; o; o >>= 1) mx = fmaxf(mx, __shfl_xor_sync(0xffffffffu, mx, o));
    if ((tid & 31) == 0) smaxw[tid >> 5] = mx;
    if (tid == 0) { sh_pref = 0u; sh_k = TOPK_; sh_cnt = 0; }
    __syncthreads();
    if (tid == 0) sh_max = fmaxf(fmaxf(smaxw[0], smaxw[1]), fmaxf(smaxw[2], smaxw[3]));

    // 4-pass MSB radix select: exact 32nd-largest key
    for (int shift = 24; shift >= 0; shift -= 8) {
        for (int i = tid; i < 256; i += nt) hist[i] = 0u;
        __syncthreads();
        unsigned pref   = sh_pref;
        unsigned maskhi = (shift == 24) ? 0u : (0xFFFFFFFFu << (shift + 8));
        for (int i = tid; i < S_; i += nt) {
            unsigned u = su[i];
            if ((u & maskhi) == pref) atomicAdd(&hist[(u >> shift) & 255u], 1u);
        }
        __syncthreads();
        if (tid == 0) {
            int kk = sh_k;
            for (int b = 255; b >= 0; b--) {
                int c = (int)hist[b];
                if (kk <= c) { sh_pref = pref | ((unsigned)b << shift); break; }
                kk -= c;
            }
            sh_k = kk;
        }
        __syncthreads();
    }
    unsigned thr = sh_pref;

    // gather survivors (scores >= kth largest, including ties)
    for (int i = tid; i < S_; i += nt) {
        if (su[i] >= thr) {
            int p = atomicAdd(&sh_cnt, 1);
            if (p < 256) sidx[p] = i;
        }
    }
    __syncthreads();
    int cnt = min(sh_cnt, 256);
    float mxv = sh_max;
    for (int i = tid; i < cnt; i += nt) sval[i] = expf(srow[sidx[i]] - mxv);
    __syncthreads();
    if (tid == 0) {
        float s = 0.f;
        for (int i = 0; i < cnt; i++) s += sval[i];
        sh_inv = 1.f / s;
    }
    __syncthreads();

    // sparse P.V: ~32 weighted V rows
    if (tid < DH_) {
        const float* V = g_v + (size_t)h * S_ * DH_;
        float acc = 0.f;
        for (int i = 0; i < cnt; i++) acc = fmaf(sval[i], V[sidx[i] * DH_ + tid], acc);
        g_att[q * INNER_ + h * DH_ + tid] = acc * sh_inv;
    }
}

// ---------------- host launcher ----------------
extern "C" void kernel_launch(void* const* d_in, const int* in_sizes, int n_in,
                              void* d_out, int out_size) {
    (void)in_sizes; (void)n_in; (void)out_size;
    const float* x    = (const float*)d_in[0];
    const float* Wqkv = (const float*)d_in[1];
    const float* Wo   = (const float*)d_in[2];
    const float* ln1g = (const float*)d_in[3];
    const float* ln1b = (const float*)d_in[4];
    const float* ln2g = (const float*)d_in[5];
    const float* ln2b = (const float*)d_in[6];
    const float* relb = (const float*)d_in[7];
    const float* w1   = (const float*)d_in[8];
    const float* b1   = (const float*)d_in[9];
    const float* w2   = (const float*)d_in[10];
    const float* b2   = (const float*)d_in[11];

    init_h_kernel<<<(S_*DIM_ + 255) / 256, 256>>>(x);

    for (int l = 0; l < NL_; l++) {
        ln_kernel<<<S_, 128>>>(ln1g + l*DIM_, ln1b + l*DIM_);
        gemm_k<0><<<dim3((3*INNER_)/64, S_/64), 256>>>(Wqkv + (size_t)l*DIM_*3*INNER_,
                                                       nullptr, 3*INNER_, DIM_);
        pb_kernel<<<NH_*S_, 64>>>(relb);
        scores_kernel<<<dim3(S_/64, S_/64, NH_), 256>>>();
        attn_row_kernel<<<NH_*S_, 128>>>();
        gemm_k<1><<<dim3(DIM_/64, S_/64), 256>>>(Wo + (size_t)l*INNER_*DIM_,
                                                 nullptr, DIM_, INNER_);
        ln_kernel<<<S_, 128>>>(ln2g + l*DIM_, ln2b + l*DIM_);
        gemm_k<2><<<dim3(HID_/64, S_/64), 256>>>(w1 + (size_t)l*DIM_*HID_,
                                                 b1 + l*HID_, HID_, DIM_);
        gemm_k<3><<<dim3(DIM_/64, S_/64), 256>>>(w2 + (size_t)l*HID_*DIM_,
                                                 b2 + l*DIM_, DIM_, HID_);
    }

    write_out_kernel<<<(S_*DIM_ + 255) / 256, 256>>>((float*)d_out);
}

// round 3
// speedup vs baseline: 1.1114x; 1.1114x over previous
#include <cuda_runtime.h>
#include <float.h>

// Problem constants (fixed by setup_inputs)
#define S_    1600
#define DIM_  384
#define NH_   6
#define DH_   64
#define INNER_ 384
#define HID_  1536
#define NL_   6
#define GW_   40
#define TOPK_ 32
#define SCALE_ 0.05103103630798288f   // 384^-0.5

// ---------------- device scratch (no allocations allowed) ----------------
__device__ float g_h[S_*DIM_];
__device__ float g_n[S_*DIM_];
__device__ float g_q[NH_*S_*DH_];
__device__ float g_k[NH_*S_*DH_];
__device__ float g_v[NH_*S_*DH_];
__device__ float g_pb[NH_*S_*64];                 // 49 buckets padded to 64
__device__ float g_rbT[64*64];                    // rel_bias transposed+padded
__device__ float g_scores[(long long)NH_*S_*S_];  // 61.4 MB
__device__ float g_att[S_*INNER_];
__device__ float g_ff1[S_*HID_];

// ---------------- trivial copy kernels ----------------
__global__ void init_h_kernel(const float* __restrict__ x) {
    int i = blockIdx.x * blockDim.x + threadIdx.x;
    if (i < S_*DIM_) g_h[i] = x[i];
}
__global__ void write_out_kernel(float* __restrict__ out) {
    int i = blockIdx.x * blockDim.x + threadIdx.x;
    if (i < S_*DIM_) out[i] = g_h[i];
}
// rbT[d][m] = rel_bias[m][d] (m<49), else 0
__global__ void rbT_kernel(const float* __restrict__ rb) {
    int i = blockIdx.x * blockDim.x + threadIdx.x;
    if (i < 64*64) {
        int d = i >> 6, m = i & 63;
        g_rbT[d*64 + m] = (m < 49) ? rb[m*64 + d] : 0.f;
    }
}

// ---------------- LayerNorm: reads g_h, writes g_n ----------------
__global__ void ln_kernel(const float* __restrict__ gamma, const float* __restrict__ beta) {
    int row = blockIdx.x;
    const float* x = g_h + row * DIM_;
    float s = 0.f, s2 = 0.f;
    for (int i = threadIdx.x; i < DIM_; i += blockDim.x) { float v = x[i]; s += v; s2 += v*v; }
    for (int o = 16; o; o >>= 1) {
        s  += __shfl_xor_sync(0xffffffffu, s,  o);
        s2 += __shfl_xor_sync(0xffffffffu, s2, o);
    }
    __shared__ float rs[4], rs2[4];
    int w = threadIdx.x >> 5;
    if ((threadIdx.x & 31) == 0) { rs[w] = s; rs2[w] = s2; }
    __syncthreads();
    s  = rs[0]  + rs[1]  + rs[2]  + rs[3];
    s2 = rs2[0] + rs2[1] + rs2[2] + rs2[3];
    float mean = s * (1.f / DIM_);
    float var  = s2 * (1.f / DIM_) - mean * mean;
    float inv  = rsqrtf(var + 1e-5f);
    for (int i = threadIdx.x; i < DIM_; i += blockDim.x)
        g_n[row*DIM_ + i] = (x[i] - mean) * inv * gamma[i] + beta[i];
}

// ---------------- shared fp32 tiled GEMM: C[M x N] = A[M x K] @ B[K x N] ----------------
// MODE 0: A=g_n,   QKV scatter epilogue (stride-3 interleave -> g_q/g_k/g_v head-major)
// MODE 1: A=g_att, g_h += acc                      (Wo + residual)
// MODE 2: A=g_n,   g_ff1 = leaky_relu(acc+bias,0.2) (FF1)
// MODE 3: A=g_ff1, g_h += acc + bias               (FF2 + residual)
// MODE 4: A=g_q,   B=g_rbT (device symbol), g_pb = acc
template<int MODE>
__global__ void __launch_bounds__(256) gemm_k(const float* __restrict__ Bp,
                                              const float* __restrict__ bias,
                                              int N, int K) {
    const float* A = (MODE == 0 || MODE == 2) ? g_n
                   : (MODE == 1) ? g_att
                   : (MODE == 3) ? g_ff1 : g_q;
    const float* B = (MODE == 4) ? g_rbT : Bp;   // device symbol resolved in device code
    __shared__ __align__(16) float As[16][68];
    __shared__ __align__(16) float Bs[16][68];
    int tid = threadIdx.x;
    int tx = tid & 15, ty = tid >> 4;
    int m0 = blockIdx.y * 64, n0 = blockIdx.x * 64;
    int arow = tid >> 2, acol = (tid & 3) * 4;
    int brow = tid >> 4, bcol = (tid & 15) * 4;
    float acc[4][4] = {};
    for (int k0 = 0; k0 < K; k0 += 16) {
        float4 av = *reinterpret_cast<const float4*>(A + (size_t)(m0 + arow) * K + k0 + acol);
        As[acol+0][arow] = av.x; As[acol+1][arow] = av.y;
        As[acol+2][arow] = av.z; As[acol+3][arow] = av.w;
        float4 bv = *reinterpret_cast<const float4*>(B + (size_t)(k0 + brow) * N + n0 + bcol);
        *reinterpret_cast<float4*>(&Bs[brow][bcol]) = bv;
        __syncthreads();
#pragma unroll
        for (int kk = 0; kk < 16; kk++) {
            float4 a4 = *reinterpret_cast<const float4*>(&As[kk][ty*4]);
            float4 b4 = *reinterpret_cast<const float4*>(&Bs[kk][tx*4]);
            float ar[4] = {a4.x, a4.y, a4.z, a4.w};
            float br[4] = {b4.x, b4.y, b4.z, b4.w};
#pragma unroll
            for (int i = 0; i < 4; i++)
#pragma unroll
                for (int j = 0; j < 4; j++)
                    acc[i][j] = fmaf(ar[i], br[j], acc[i][j]);
        }
        __syncthreads();
    }
#pragma unroll
    for (int i = 0; i < 4; i++) {
        int m = m0 + ty*4 + i;
#pragma unroll
        for (int j = 0; j < 4; j++) {
            int n = n0 + tx*4 + j;
            float v = acc[i][j];
            if (MODE == 0) {
                int idx = n / 3, r = n - idx * 3;      // qkv[..., r::3] -> (NH,DH)
                int hh = idx >> 6, d = idx & 63;
                float* dst = (r == 0) ? g_q : (r == 1) ? g_k : g_v;
                dst[(hh * S_ + m) * DH_ + d] = v;
            } else if (MODE == 1) {
                g_h[m * DIM_ + n] += v;
            } else if (MODE == 2) {
                float t = v + bias[n];
                g_ff1[m * HID_ + n] = t > 0.f ? t : 0.2f * t;
            } else if (MODE == 3) {
                g_h[m * DIM_ + n] += v + bias[n];
            } else {
                g_pb[m * 64 + n] = v;
            }
        }
    }
}

// ---------------- scores[h,q,k] = (q.k + pb[buck(q,k)]) * SCALE ----------------
__global__ void __launch_bounds__(256) scores_kernel() {
    int h = blockIdx.z;
    const float* Q  = g_q + (size_t)h * S_ * DH_;
    const float* Km = g_k + (size_t)h * S_ * DH_;
    __shared__ __align__(16) float Qs[16][68];
    __shared__ __align__(16) float Ks[16][68];
    int tid = threadIdx.x;
    int tx = tid & 15, ty = tid >> 4;
    int m0 = blockIdx.y * 64, n0 = blockIdx.x * 64;
    int row = tid >> 2, col = (tid & 3) * 4;
    float acc[4][4] = {};
    for (int k0 = 0; k0 < DH_; k0 += 16) {
        float4 qv4 = *reinterpret_cast<const float4*>(Q + (size_t)(m0 + row) * DH_ + k0 + col);
        Qs[col+0][row] = qv4.x; Qs[col+1][row] = qv4.y;
        Qs[col+2][row] = qv4.z; Qs[col+3][row] = qv4.w;
        float4 kv4 = *reinterpret_cast<const float4*>(Km + (size_t)(n0 + row) * DH_ + k0 + col);
        Ks[col+0][row] = kv4.x; Ks[col+1][row] = kv4.y;
        Ks[col+2][row] = kv4.z; Ks[col+3][row] = kv4.w;
        __syncthreads();
#pragma unroll
        for (int kk = 0; kk < 16; kk++) {
            float4 a4 = *reinterpret_cast<const float4*>(&Qs[kk][ty*4]);
            float4 b4 = *reinterpret_cast<const float4*>(&Ks[kk][tx*4]);
            float ar[4] = {a4.x, a4.y, a4.z, a4.w};
            float br[4] = {b4.x, b4.y, b4.z, b4.w};
#pragma unroll
            for (int i = 0; i < 4; i++)
#pragma unroll
                for (int j = 0; j < 4; j++)
                    acc[i][j] = fmaf(ar[i], br[j], acc[i][j]);
        }
        __syncthreads();
    }
#pragma unroll
    for (int i = 0; i < 4; i++) {
        int q = m0 + ty*4 + i;
        int qv = q / GW_, qh = q - qv * GW_;
        const float* pbq = g_pb + ((size_t)h * S_ + q) * 64;
        float* srow = g_scores + ((size_t)h * S_ + q) * S_;
#pragma unroll
        for (int j = 0; j < 4; j++) {
            int kq = n0 + tx*4 + j;
            int kv = kq / GW_, kh = kq - qv * 0 - kv * 0 + kh * 0 + (kq - kv * GW_); // placeholder removed below
            (void)kv;
            kh = kq - (kq / GW_) * GW_;
            kv = kq / GW_;
            int dv = kv - qv, dh = kh - qh;
            int ad = (dv < 0 ? -dv : dv) + (dh < 0 ? -dh : dh);
            int m = (ad <= 3) ? ((dv + 3) * 7 + (dh + 3)) : 0;
            srow[kq] = (acc[i][j] + pbq[m]) * SCALE_;
        }
    }
}

// ---------------- per-row: exact top-32 radix select + softmax + sparse P.V ----------------
__global__ void __launch_bounds__(256) attn_row_kernel() {
    int bx = blockIdx.x;                 // h*S + q
    int h = bx / S_, q = bx - h * S_;
    const float* srow = g_scores + (size_t)bx * S_;
    __shared__ unsigned su[S_];
    __shared__ unsigned hist[256];
    __shared__ int   sidx[256];
    __shared__ float sval[256];
    __shared__ float smaxw[8];
    __shared__ float ssum[8];
    __shared__ unsigned sh_pref;
    __shared__ int sh_k, sh_cnt;
    __shared__ float sh_max, sh_inv;
    int tid = threadIdx.x, nt = blockDim.x;
    int wid = tid >> 5, lane = tid & 31;

    // load + order-preserving float->uint key + row max (vectorized)
    float mx = -FLT_MAX;
    const float4* srow4 = reinterpret_cast<const float4*>(srow);
    for (int i = tid; i < S_/4; i += nt) {
        float4 v4 = srow4[i];
        float vv[4] = {v4.x, v4.y, v4.z, v4.w};
#pragma unroll
        for (int j = 0; j < 4; j++) {
            unsigned b = __float_as_uint(vv[j]);
            su[i*4 + j] = (b & 0x80000000u) ? ~b : (b | 0x80000000u);
            mx = fmaxf(mx, vv[j]);
        }
    }
    for (int o = 16; o; o >>= 1) mx = fmaxf(mx, __shfl_xor_sync(0xffffffffu, mx, o));
    if (lane == 0) smaxw[wid] = mx;
    if (tid == 0) { sh_pref = 0u; sh_k = TOPK_; sh_cnt = 0; }
    __syncthreads();
    if (tid == 0) {
        float m = smaxw[0];
#pragma unroll
        for (int w = 1; w < 8; w++) m = fmaxf(m, smaxw[w]);
        sh_max = m;
    }

    // 4-pass MSB radix select: exact 32nd-largest key
    for (int shift = 24; shift >= 0; shift -= 8) {
        if (tid < 256) hist[tid] = 0u;
        __syncthreads();
        unsigned pref   = sh_pref;
        unsigned maskhi = (shift == 24) ? 0u : (0xFFFFFFFFu << (shift + 8));
        for (int i = tid; i < S_; i += nt) {
            unsigned u = su[i];
            if ((u & maskhi) == pref) atomicAdd(&hist[(u >> shift) & 255u], 1u);
        }
        __syncthreads();
        if (tid == 0) {
            int kk = sh_k;
            for (int b = 255; b >= 0; b--) {
                int c = (int)hist[b];
                if (kk <= c) { sh_pref = pref | ((unsigned)b << shift); break; }
                kk -= c;
            }
            sh_k = kk;
        }
        __syncthreads();
    }
    unsigned thr = sh_pref;
    float mxv = sh_max;

    // gather survivors; recover exact score from key (no global reload)
    for (int i = tid; i < S_; i += nt) {
        unsigned u = su[i];
        if (u >= thr) {
            int p = atomicAdd(&sh_cnt, 1);
            if (p < 256) {
                float v = (u & 0x80000000u) ? __uint_as_float(u ^ 0x80000000u)
                                            : __uint_as_float(~u);
                sidx[p] = i;
                sval[p] = expf(v - mxv);
            }
        }
    }
    __syncthreads();
    int cnt = min(sh_cnt, 256);

    // parallel sum of exp weights
    {
        float s = 0.f;
        for (int i = tid; i < cnt; i += nt) s += sval[i];
        for (int o = 16; o; o >>= 1) s += __shfl_xor_sync(0xffffffffu, s, o);
        if (lane == 0) ssum[wid] = s;
        __syncthreads();
        if (tid == 0) {
            float t = ssum[0];
#pragma unroll
            for (int w = 1; w < 8; w++) t += ssum[w];
            sh_inv = 1.f / t;
        }
        __syncthreads();
    }

    // sparse P.V: ~32 weighted V rows
    if (tid < DH_) {
        const float* V = g_v + (size_t)h * S_ * DH_;
        float acc = 0.f;
        for (int i = 0; i < cnt; i++) acc = fmaf(sval[i], V[sidx[i] * DH_ + tid], acc);
        g_att[q * INNER_ + h * DH_ + tid] = acc * sh_inv;
    }
}

// ---------------- host launcher ----------------
extern "C" void kernel_launch(void* const* d_in, const int* in_sizes, int n_in,
                              void* d_out, int out_size) {
    (void)in_sizes; (void)n_in; (void)out_size;
    const float* x    = (const float*)d_in[0];
    const float* Wqkv = (const float*)d_in[1];
    const float* Wo   = (const float*)d_in[2];
    const float* ln1g = (const float*)d_in[3];
    const float* ln1b = (const float*)d_in[4];
    const float* ln2g = (const float*)d_in[5];
    const float* ln2b = (const float*)d_in[6];
    const float* relb = (const float*)d_in[7];
    const float* w1   = (const float*)d_in[8];
    const float* b1   = (const float*)d_in[9];
    const float* w2   = (const float*)d_in[10];
    const float* b2   = (const float*)d_in[11];

    init_h_kernel<<<(S_*DIM_ + 255) / 256, 256>>>(x);
    rbT_kernel<<<16, 256>>>(relb);

    for (int l = 0; l < NL_; l++) {
        ln_kernel<<<S_, 128>>>(ln1g + l*DIM_, ln1b + l*DIM_);
        gemm_k<0><<<dim3((3*INNER_)/64, S_/64), 256>>>(Wqkv + (size_t)l*DIM_*3*INNER_,
                                                       nullptr, 3*INNER_, DIM_);
        gemm_k<4><<<dim3(1, (NH_*S_)/64), 256>>>(nullptr, nullptr, 64, 64);
        scores_kernel<<<dim3(S_/64, S_/64, NH_), 256>>>();
        attn_row_kernel<<<NH_*S_, 256>>>();
        gemm_k<1><<<dim3(DIM_/64, S_/64), 256>>>(Wo + (size_t)l*INNER_*DIM_,
                                                 nullptr, DIM_, INNER_);
        ln_kernel<<<S_, 128>>>(ln2g + l*DIM_, ln2b + l*DIM_);
        gemm_k<2><<<dim3(HID_/64, S_/64), 256>>>(w1 + (size_t)l*DIM_*HID_,
                                                 b1 + l*HID_, HID_, DIM_);
        gemm_k<3><<<dim3(DIM_/64, S_/64), 256>>>(w2 + (size_t)l*HID_*DIM_,
                                                 b2 + l*DIM_, DIM_, HID_);
    }

    write_out_kernel<<<(S_*DIM_ + 255) / 256, 256>>>((float*)d_out);
}